// round 1
// baseline (speedup 1.0000x reference)
#include <cuda_runtime.h>
#include <cuda_bf16.h>
#include <cstdint>

// Problem constants (fixed shapes for GTLayer_34961033790001)
#define NND   4096                 // num nodes
#define CIN   5
#define COUT  2
#define NEDGE 262144
#define NNSQ  ((size_t)NND * (size_t)NND)   // 16,777,216

// Scratch: mixed dense matrices A[o], B[o]  (o = 0,1).  2 * 64MB each = 268 MB.
__device__ float g_A[COUT * NNSQ];
__device__ float g_B[COUT * NNSQ];
__device__ float g_f1[COUT * CIN];
__device__ float g_f2[COUT * CIN];

// ---------------------------------------------------------------------------
// 1) Zero the accumulation buffers (must run every launch: graph replays reuse them)
// ---------------------------------------------------------------------------
__global__ void zero_all_kernel() {
    size_t i = (size_t)blockIdx.x * blockDim.x + threadIdx.x;
    size_t stride = (size_t)gridDim.x * blockDim.x;
    size_t n4 = (COUT * NNSQ) / 4;
    float4 z = make_float4(0.f, 0.f, 0.f, 0.f);
    float4* a = reinterpret_cast<float4*>(g_A);
    float4* b = reinterpret_cast<float4*>(g_B);
    for (size_t k = i; k < n4; k += stride) {
        a[k] = z;
        b[k] = z;
    }
}

// ---------------------------------------------------------------------------
// 2) Softmax of the two [COUT, CIN] weight matrices (tiny). Also writes the
//    f1/f2 tail of the output buffer when the harness output includes them.
// ---------------------------------------------------------------------------
__global__ void softmax_kernel(const float* __restrict__ w1,
                               const float* __restrict__ w2,
                               float* __restrict__ out_tail /* may be null */) {
    if (threadIdx.x != 0 || blockIdx.x != 0) return;
    for (int o = 0; o < COUT; o++) {
        // w1 -> f1
        {
            float m = -1e30f;
            for (int c = 0; c < CIN; c++) m = fmaxf(m, w1[o * CIN + c]);
            float s = 0.f;
            float e[CIN];
            for (int c = 0; c < CIN; c++) { e[c] = expf(w1[o * CIN + c] - m); s += e[c]; }
            float inv = 1.f / s;
            for (int c = 0; c < CIN; c++) {
                float f = e[c] * inv;
                g_f1[o * CIN + c] = f;
                if (out_tail) out_tail[o * CIN + c] = f;
            }
        }
        // w2 -> f2
        {
            float m = -1e30f;
            for (int c = 0; c < CIN; c++) m = fmaxf(m, w2[o * CIN + c]);
            float s = 0.f;
            float e[CIN];
            for (int c = 0; c < CIN; c++) { e[c] = expf(w2[o * CIN + c] - m); s += e[c]; }
            float inv = 1.f / s;
            for (int c = 0; c < CIN; c++) {
                float f = e[c] * inv;
                g_f2[o * CIN + c] = f;
                if (out_tail) out_tail[COUT * CIN + o * CIN + c] = f;
            }
        }
    }
}

// ---------------------------------------------------------------------------
// 3) Fused scatter: each edge (c, e) with value v contributes
//      A[o][i,j] += f1[o,c]*v,  B[o][i,j] += f2[o,c]*v   for o in {0,1}.
//    This skips materializing the 5 dense Adj matrices entirely.
// ---------------------------------------------------------------------------
__global__ void scatter_kernel(const int* __restrict__ edge_index,
                               const float* __restrict__ edge_value) {
    int idx = blockIdx.x * blockDim.x + threadIdx.x;
    if (idx >= CIN * NEDGE) return;
    int c = idx / NEDGE;
    int e = idx - c * NEDGE;
    int i = edge_index[(size_t)(c * 2) * NEDGE + e];
    int j = edge_index[(size_t)(c * 2 + 1) * NEDGE + e];
    float v = edge_value[(size_t)c * NEDGE + e];
    size_t off = (size_t)i * NND + j;
#pragma unroll
    for (int o = 0; o < COUT; o++) {
        atomicAdd(&g_A[(size_t)o * NNSQ + off], g_f1[o * CIN + c] * v);
        atomicAdd(&g_B[(size_t)o * NNSQ + off], g_f2[o * CIN + c] * v);
    }
}

// ---------------------------------------------------------------------------
// 4) Dense fp32 GEMM: H[o] = A[o] @ B[o], both row-major 4096x4096.
//    128x128 tile, BK=8, 8x8 per thread, 256 threads, vectorized loads.
// ---------------------------------------------------------------------------
#define BM 128
#define BN 128
#define BK 8
__global__ void __launch_bounds__(256, 2) sgemm_kernel(float* __restrict__ C) {
    const int o = blockIdx.z;
    const float* __restrict__ A = g_A + (size_t)o * NNSQ;
    const float* __restrict__ B = g_B + (size_t)o * NNSQ;
    float* __restrict__ Co = C + (size_t)o * NNSQ;

    __shared__ float As[BK][BM];
    __shared__ float Bs[BK][BN];

    const int tid = threadIdx.x;
    const int tx = tid & 15;        // 0..15  -> column group
    const int ty = tid >> 4;        // 0..15  -> row group
    const int rowBase = blockIdx.y * BM;
    const int colBase = blockIdx.x * BN;

    // A-tile load mapping: 128 rows x 8 k  (two float4 per row, one per thread-pair)
    const int aRow = tid >> 1;             // 0..127
    const int aK4  = (tid & 1) * 4;        // 0 or 4
    // B-tile load mapping: 8 rows x 128 cols (float4 per thread)
    const int bRow  = tid >> 5;            // 0..7
    const int bCol4 = (tid & 31) * 4;      // 0..124

    float acc[8][8];
#pragma unroll
    for (int m = 0; m < 8; m++)
#pragma unroll
        for (int n = 0; n < 8; n++) acc[m][n] = 0.f;

    const size_t aBase = (size_t)(rowBase + aRow) * NND;

    for (int k0 = 0; k0 < NND; k0 += BK) {
        float4 av = *reinterpret_cast<const float4*>(&A[aBase + k0 + aK4]);
        As[aK4 + 0][aRow] = av.x;
        As[aK4 + 1][aRow] = av.y;
        As[aK4 + 2][aRow] = av.z;
        As[aK4 + 3][aRow] = av.w;
        *reinterpret_cast<float4*>(&Bs[bRow][bCol4]) =
            *reinterpret_cast<const float4*>(&B[(size_t)(k0 + bRow) * NND + colBase + bCol4]);
        __syncthreads();

#pragma unroll
        for (int k = 0; k < BK; k++) {
            float ra[8], rb[8];
            float4 a0 = *reinterpret_cast<const float4*>(&As[k][ty * 8]);
            float4 a1 = *reinterpret_cast<const float4*>(&As[k][ty * 8 + 4]);
            ra[0] = a0.x; ra[1] = a0.y; ra[2] = a0.z; ra[3] = a0.w;
            ra[4] = a1.x; ra[5] = a1.y; ra[6] = a1.z; ra[7] = a1.w;
            float4 b0 = *reinterpret_cast<const float4*>(&Bs[k][tx * 8]);
            float4 b1 = *reinterpret_cast<const float4*>(&Bs[k][tx * 8 + 4]);
            rb[0] = b0.x; rb[1] = b0.y; rb[2] = b0.z; rb[3] = b0.w;
            rb[4] = b1.x; rb[5] = b1.y; rb[6] = b1.z; rb[7] = b1.w;
#pragma unroll
            for (int m = 0; m < 8; m++)
#pragma unroll
                for (int n = 0; n < 8; n++)
                    acc[m][n] = fmaf(ra[m], rb[n], acc[m][n]);
        }
        __syncthreads();
    }

    // Store 8x8 per thread, vectorized
#pragma unroll
    for (int m = 0; m < 8; m++) {
        size_t r = (size_t)(rowBase + ty * 8 + m) * NND + colBase + tx * 8;
        float4 v0 = make_float4(acc[m][0], acc[m][1], acc[m][2], acc[m][3]);
        float4 v1 = make_float4(acc[m][4], acc[m][5], acc[m][6], acc[m][7]);
        *reinterpret_cast<float4*>(&Co[r])     = v0;
        *reinterpret_cast<float4*>(&Co[r + 4]) = v1;
    }
}

// ---------------------------------------------------------------------------
// kernel_launch
// Inputs (metadata order): edge_index int32 [5,2,262144], edge_value f32
// [5,262144], weight1 f32 [2,5], weight2 f32 [2,5], num_nodes int32 [1].
// Output: concat(H [2,4096,4096], f1 [2,5], f2 [2,5]) as f32.
// ---------------------------------------------------------------------------
extern "C" void kernel_launch(void* const* d_in, const int* in_sizes, int n_in,
                              void* d_out, int out_size) {
    const int*   edge_index = (const int*)d_in[0];
    const float* edge_value = (const float*)d_in[1];
    const float* weight1    = (const float*)d_in[2];
    const float* weight2    = (const float*)d_in[3];

    float* out = (float*)d_out;
    const size_t h_elems = (size_t)COUT * NNSQ;
    float* out_tail = ((size_t)out_size >= h_elems + 2 * COUT * CIN)
                          ? (out + h_elems) : nullptr;

    // 1) zero mixed adjacency buffers
    zero_all_kernel<<<2048, 256>>>();
    // 2) softmax weights (also writes f1/f2 output tail)
    softmax_kernel<<<1, 32>>>(weight1, weight2, out_tail);
    // 3) fused channel-mix scatter
    {
        int total = CIN * NEDGE;
        scatter_kernel<<<(total + 255) / 256, 256>>>(edge_index, edge_value);
    }
    // 4) per-channel dense GEMM -> H
    {
        dim3 grid(NND / BN, NND / BM, COUT);
        sgemm_kernel<<<grid, 256>>>(out);
    }
}

// round 3
// speedup vs baseline: 2.5789x; 2.5789x over previous
#include <cuda_runtime.h>
#include <cuda_bf16.h>
#include <cstdint>

// Problem constants (fixed shapes for GTLayer_34961033790001)
#define NND   4096
#define CIN   5
#define COUT  2
#define NEDGE 262144
#define NNSQ  ((size_t)NND * (size_t)NND)

__device__ float g_A[COUT * NNSQ];
__device__ float g_B[COUT * NNSQ];
__device__ float g_f1[COUT * CIN];
__device__ float g_f2[COUT * CIN];

// ---------------------------------------------------------------------------
// 1) Zero accumulation buffers (graph replays reuse them)
// ---------------------------------------------------------------------------
__global__ void zero_all_kernel() {
    size_t i = (size_t)blockIdx.x * blockDim.x + threadIdx.x;
    size_t stride = (size_t)gridDim.x * blockDim.x;
    size_t n4 = (COUT * NNSQ) / 4;
    float4 z = make_float4(0.f, 0.f, 0.f, 0.f);
    float4* a = reinterpret_cast<float4*>(g_A);
    float4* b = reinterpret_cast<float4*>(g_B);
    for (size_t k = i; k < n4; k += stride) {
        a[k] = z;
        b[k] = z;
    }
}

// ---------------------------------------------------------------------------
// 2) Softmax of [COUT, CIN] weights (tiny) + output tail
// ---------------------------------------------------------------------------
__global__ void softmax_kernel(const float* __restrict__ w1,
                               const float* __restrict__ w2,
                               float* __restrict__ out_tail) {
    if (threadIdx.x != 0 || blockIdx.x != 0) return;
    for (int o = 0; o < COUT; o++) {
        {
            float m = -1e30f;
            for (int c = 0; c < CIN; c++) m = fmaxf(m, w1[o * CIN + c]);
            float s = 0.f, e[CIN];
            for (int c = 0; c < CIN; c++) { e[c] = expf(w1[o * CIN + c] - m); s += e[c]; }
            float inv = 1.f / s;
            for (int c = 0; c < CIN; c++) {
                float f = e[c] * inv;
                g_f1[o * CIN + c] = f;
                if (out_tail) out_tail[o * CIN + c] = f;
            }
        }
        {
            float m = -1e30f;
            for (int c = 0; c < CIN; c++) m = fmaxf(m, w2[o * CIN + c]);
            float s = 0.f, e[CIN];
            for (int c = 0; c < CIN; c++) { e[c] = expf(w2[o * CIN + c] - m); s += e[c]; }
            float inv = 1.f / s;
            for (int c = 0; c < CIN; c++) {
                float f = e[c] * inv;
                g_f2[o * CIN + c] = f;
                if (out_tail) out_tail[COUT * CIN + o * CIN + c] = f;
            }
        }
    }
}

// ---------------------------------------------------------------------------
// 3) Fused channel-mix scatter (skips materializing the 5 dense Adj)
// ---------------------------------------------------------------------------
__global__ void scatter_kernel(const int* __restrict__ edge_index,
                               const float* __restrict__ edge_value) {
    int idx = blockIdx.x * blockDim.x + threadIdx.x;
    if (idx >= CIN * NEDGE) return;
    int c = idx / NEDGE;
    int e = idx - c * NEDGE;
    int i = edge_index[(size_t)(c * 2) * NEDGE + e];
    int j = edge_index[(size_t)(c * 2 + 1) * NEDGE + e];
    float v = edge_value[(size_t)c * NEDGE + e];
    size_t off = (size_t)i * NND + j;
#pragma unroll
    for (int o = 0; o < COUT; o++) {
        atomicAdd(&g_A[(size_t)o * NNSQ + off], g_f1[o * CIN + c] * v);
        atomicAdd(&g_B[(size_t)o * NNSQ + off], g_f2[o * CIN + c] * v);
    }
}

// ---------------------------------------------------------------------------
// 4) Round A,B to tf32 (round-to-nearest) in place. cvt.rna.tf32.f32 has a
//    .b32 destination register in PTX -> "=r" constraint, reinterpret bits.
// ---------------------------------------------------------------------------
__device__ __forceinline__ float to_tf32(float x) {
    uint32_t y;
    asm("cvt.rna.tf32.f32 %0, %1;" : "=r"(y) : "f"(x));
    return __uint_as_float(y);
}
__global__ void round_tf32_kernel() {
    size_t i = (size_t)blockIdx.x * blockDim.x + threadIdx.x;
    size_t stride = (size_t)gridDim.x * blockDim.x;
    size_t n4 = (COUT * NNSQ) / 4;
    float4* a = reinterpret_cast<float4*>(g_A);
    float4* b = reinterpret_cast<float4*>(g_B);
    for (size_t k = i; k < n4; k += stride) {
        float4 v = a[k];
        v.x = to_tf32(v.x); v.y = to_tf32(v.y); v.z = to_tf32(v.z); v.w = to_tf32(v.w);
        a[k] = v;
        float4 w = b[k];
        w.x = to_tf32(w.x); w.y = to_tf32(w.y); w.z = to_tf32(w.z); w.w = to_tf32(w.w);
        b[k] = w;
    }
}

// ---------------------------------------------------------------------------
// 5) tf32 tensor-core GEMM: H[o] = A[o] @ B[o], 4096x4096x4096.
//    128x128x16 block tile, 8 warps (2x4), 64x32 warp tile of m16n8k8 mma,
//    cp.async double buffering.
// ---------------------------------------------------------------------------
#define BM 128
#define BN 128
#define BKT 16
#define AS_STRIDE 20    // BK + 4 pad -> conflict-free A fragment loads
#define BS_STRIDE 136   // BN + 8 pad -> conflict-free B fragment loads

__device__ __forceinline__ void cp_async16(uint32_t s, const void* g) {
    asm volatile("cp.async.ca.shared.global [%0], [%1], 16;\n" :: "r"(s), "l"(g));
}
__device__ __forceinline__ void cp_commit() {
    asm volatile("cp.async.commit_group;\n");
}
template <int N>
__device__ __forceinline__ void cp_wait() {
    asm volatile("cp.async.wait_group %0;\n" :: "n"(N));
}

__device__ __forceinline__ void mma_tf32(float& c0, float& c1, float& c2, float& c3,
                                         uint32_t a0, uint32_t a1, uint32_t a2, uint32_t a3,
                                         uint32_t b0, uint32_t b1) {
    asm volatile(
        "mma.sync.aligned.m16n8k8.row.col.f32.tf32.tf32.f32 "
        "{%0,%1,%2,%3}, {%4,%5,%6,%7}, {%8,%9}, {%0,%1,%2,%3};"
        : "+f"(c0), "+f"(c1), "+f"(c2), "+f"(c3)
        : "r"(a0), "r"(a1), "r"(a2), "r"(a3), "r"(b0), "r"(b1));
}

__global__ void __launch_bounds__(256) tf32_gemm_kernel(float* __restrict__ C) {
    const int o = blockIdx.z;
    const float* __restrict__ A = g_A + (size_t)o * NNSQ;
    const float* __restrict__ B = g_B + (size_t)o * NNSQ;
    float* __restrict__ Co = C + (size_t)o * NNSQ;

    __shared__ float As[2][BM * AS_STRIDE];   // 2*128*20*4B = 20 KB
    __shared__ float Bs[2][BKT * BS_STRIDE];  // 2*16*136*4B = 17 KB

    const int tid  = threadIdx.x;
    const int lane = tid & 31;
    const int warp = tid >> 5;
    const int wm = (warp >> 2) * 64;   // warp m offset in tile (0 or 64)
    const int wn = (warp & 3) * 32;    // warp n offset in tile (0..96)
    const int g  = lane >> 2;          // groupID 0..7
    const int t  = lane & 3;           // thread-in-group 0..3

    const int rowBase = blockIdx.y * BM;
    const int colBase = blockIdx.x * BN;

    uint32_t asBase = (uint32_t)__cvta_generic_to_shared(&As[0][0]);
    uint32_t bsBase = (uint32_t)__cvta_generic_to_shared(&Bs[0][0]);
    const uint32_t asBufBytes = BM * AS_STRIDE * 4;
    const uint32_t bsBufBytes = BKT * BS_STRIDE * 4;

    float acc[4][4][4];
#pragma unroll
    for (int mt = 0; mt < 4; mt++)
#pragma unroll
        for (int nt = 0; nt < 4; nt++)
#pragma unroll
            for (int r = 0; r < 4; r++) acc[mt][nt][r] = 0.f;

    auto load_tile = [&](int k0, int buf) {
#pragma unroll
        for (int i = 0; i < 2; i++) {
            int id = tid * 2 + i;
            // A: 128 rows x 16 k  -> id: row=id>>2, seg=id&3
            int ar = id >> 2, aseg = id & 3;
            cp_async16(asBase + buf * asBufBytes + (ar * AS_STRIDE + aseg * 4) * 4,
                       &A[(size_t)(rowBase + ar) * NND + k0 + aseg * 4]);
            // B: 16 rows x 128 cols -> id: row=id>>5, seg=id&31
            int br = id >> 5, bseg = id & 31;
            cp_async16(bsBase + buf * bsBufBytes + (br * BS_STRIDE + bseg * 4) * 4,
                       &B[(size_t)(k0 + br) * NND + colBase + bseg * 4]);
        }
        cp_commit();
    };

    const int NT = NND / BKT;  // 256
    load_tile(0, 0);

    int buf = 0;
    for (int kt = 0; kt < NT; kt++) {
        if (kt + 1 < NT) {
            load_tile((kt + 1) * BKT, buf ^ 1);
            cp_wait<1>();
        } else {
            cp_wait<0>();
        }
        __syncthreads();

        const float* as = As[buf];
        const float* bs = Bs[buf];
#pragma unroll
        for (int ks = 0; ks < BKT; ks += 8) {
            uint32_t ra[4][4];
#pragma unroll
            for (int mt = 0; mt < 4; mt++) {
                int r0 = wm + mt * 16;
                ra[mt][0] = __float_as_uint(as[(r0 + g)     * AS_STRIDE + ks + t]);
                ra[mt][1] = __float_as_uint(as[(r0 + g + 8) * AS_STRIDE + ks + t]);
                ra[mt][2] = __float_as_uint(as[(r0 + g)     * AS_STRIDE + ks + t + 4]);
                ra[mt][3] = __float_as_uint(as[(r0 + g + 8) * AS_STRIDE + ks + t + 4]);
            }
            uint32_t rb[4][2];
#pragma unroll
            for (int nt = 0; nt < 4; nt++) {
                int c0 = wn + nt * 8 + g;
                rb[nt][0] = __float_as_uint(bs[(ks + t)     * BS_STRIDE + c0]);
                rb[nt][1] = __float_as_uint(bs[(ks + t + 4) * BS_STRIDE + c0]);
            }
#pragma unroll
            for (int mt = 0; mt < 4; mt++)
#pragma unroll
                for (int nt = 0; nt < 4; nt++)
                    mma_tf32(acc[mt][nt][0], acc[mt][nt][1], acc[mt][nt][2], acc[mt][nt][3],
                             ra[mt][0], ra[mt][1], ra[mt][2], ra[mt][3],
                             rb[nt][0], rb[nt][1]);
        }
        __syncthreads();
        buf ^= 1;
    }

    // Epilogue: c0,c1 at (row=g, col=2t,2t+1), c2,c3 at row+8
#pragma unroll
    for (int mt = 0; mt < 4; mt++) {
#pragma unroll
        for (int nt = 0; nt < 4; nt++) {
            int row = rowBase + wm + mt * 16 + g;
            int col = colBase + wn + nt * 8 + 2 * t;
            float2 v01 = make_float2(acc[mt][nt][0], acc[mt][nt][1]);
            float2 v23 = make_float2(acc[mt][nt][2], acc[mt][nt][3]);
            *reinterpret_cast<float2*>(&Co[(size_t)row * NND + col]) = v01;
            *reinterpret_cast<float2*>(&Co[(size_t)(row + 8) * NND + col]) = v23;
        }
    }
}

// ---------------------------------------------------------------------------
// kernel_launch
// Inputs: edge_index int32 [5,2,262144], edge_value f32 [5,262144],
//         weight1 f32 [2,5], weight2 f32 [2,5], num_nodes int32 [1].
// Output: concat(H [2,4096,4096], f1 [2,5], f2 [2,5]) f32.
// ---------------------------------------------------------------------------
extern "C" void kernel_launch(void* const* d_in, const int* in_sizes, int n_in,
                              void* d_out, int out_size) {
    const int*   edge_index = (const int*)d_in[0];
    const float* edge_value = (const float*)d_in[1];
    const float* weight1    = (const float*)d_in[2];
    const float* weight2    = (const float*)d_in[3];

    float* out = (float*)d_out;
    const size_t h_elems = (size_t)COUT * NNSQ;
    float* out_tail = ((size_t)out_size >= h_elems + 2 * COUT * CIN)
                          ? (out + h_elems) : nullptr;

    zero_all_kernel<<<2048, 256>>>();
    softmax_kernel<<<1, 32>>>(weight1, weight2, out_tail);
    {
        int total = CIN * NEDGE;
        scatter_kernel<<<(total + 255) / 256, 256>>>(edge_index, edge_value);
    }
    round_tf32_kernel<<<2048, 256>>>();
    {
        dim3 grid(NND / BN, NND / BM, COUT);
        tf32_gemm_kernel<<<grid, 256>>>(out);
    }
}